// round 3
// baseline (speedup 1.0000x reference)
#include <cuda_runtime.h>
#include <cuda_bf16.h>

// Problem constants (from reference):
//   B = 128 rows, L = 262144 input cols
//   CROP_NUM = 26214, OUT_LEN = 235930
//   out[i, j] = audio[i, j]             for j <  starts[i]
//   out[i, j] = audio[i, j + CROP_NUM]  for j >= starts[i]

#define B_ROWS   128
#define L_IN     262144u
#define CROP_NUM 26214u
#define OUT_LEN  235930u
// TOTAL = 128 * 235930 = 30199040, divisible by 4
#define TOTAL_OUT 30199040u
#define NVEC      (TOTAL_OUT / 4u)   // 7549760

__global__ __launch_bounds__(256)
void Crop_21345987461560_kernel(const float* __restrict__ audio,
                                const int*   __restrict__ starts,
                                float*       __restrict__ out)
{
    unsigned int t = blockIdx.x * blockDim.x + threadIdx.x;
    if (t >= NVEC) return;

    unsigned int f0 = t * 4u;                    // flat output index of lane 0
    unsigned int i  = f0 / OUT_LEN;              // row  (IMAD.HI const-div)
    unsigned int j0 = f0 - i * OUT_LEN;          // col within row

    if (j0 + 3u < OUT_LEN) {
        // Fast path: all 4 elements in the same row.
        const unsigned int start = (unsigned int)__ldg(&starts[i]);
        const float* __restrict__ rowp = audio + (size_t)i * L_IN;

        float4 v;
        unsigned int j;
        j = j0;      v.x = __ldg(&rowp[j + (j >= start ? CROP_NUM : 0u)]);
        j = j0 + 1u; v.y = __ldg(&rowp[j + (j >= start ? CROP_NUM : 0u)]);
        j = j0 + 2u; v.z = __ldg(&rowp[j + (j >= start ? CROP_NUM : 0u)]);
        j = j0 + 3u; v.w = __ldg(&rowp[j + (j >= start ? CROP_NUM : 0u)]);

        reinterpret_cast<float4*>(out)[t] = v;
    } else {
        // Slow path: float4 straddles a row boundary (<=127 vectors total).
        #pragma unroll
        for (int k = 0; k < 4; ++k) {
            unsigned int f  = f0 + (unsigned int)k;
            unsigned int ii = f / OUT_LEN;
            unsigned int jj = f - ii * OUT_LEN;
            unsigned int st = (unsigned int)__ldg(&starts[ii]);
            out[f] = __ldg(&audio[(size_t)ii * L_IN + jj + (jj >= st ? CROP_NUM : 0u)]);
        }
    }
}

extern "C" void kernel_launch(void* const* d_in, const int* in_sizes, int n_in,
                              void* d_out, int out_size)
{
    const float* audio  = (const float*)d_in[0];   // [128, 262144] float32
    const int*   starts = (const int*)d_in[1];     // [128] int32
    float*       out    = (float*)d_out;           // [128, 235930] float32

    const unsigned int threads = 256;
    const unsigned int blocks  = (NVEC + threads - 1) / threads;  // 29492
    Crop_21345987461560_kernel<<<blocks, threads>>>(audio, starts, out);
}

// round 4
// speedup vs baseline: 1.0502x; 1.0502x over previous
#include <cuda_runtime.h>
#include <cuda_bf16.h>

// Problem constants:
//   B = 128 rows, L = 262144 input cols
//   CROP_NUM = 26214, OUT_LEN = 235930
//   out[i, j] = audio[i, j]             for j <  starts[i]
//   out[i, j] = audio[i, j + CROP_NUM]  for j >= starts[i]

#define L_IN     262144u
#define CROP_NUM 26214u
#define OUT_LEN  235930u
#define TOTAL_OUT 30199040u              // 128 * 235930, divisible by 4
#define NVEC      (TOTAL_OUT / 4u)       // 7549760 float4 vectors
#define HALFVEC   (NVEC / 2u)            // 3774880 (NVEC is even)

__device__ __forceinline__ void process_vec(unsigned int t,
                                            const float* __restrict__ audio,
                                            const int*   __restrict__ starts,
                                            float*       __restrict__ out)
{
    unsigned int f0 = t * 4u;                    // flat output index
    unsigned int i  = f0 / OUT_LEN;              // row (IMAD.HI const-div)
    unsigned int j0 = f0 - i * OUT_LEN;          // col within row (always even)
    const float* __restrict__ rowp = audio + (size_t)i * L_IN;

    if (j0 + 3u < OUT_LEN) {
        const unsigned int start = (unsigned int)__ldg(&starts[i]);
        float4 v;
        if (j0 + 3u < start) {
            // Fully pre-crop: contiguous, 8B-aligned (j0 even) -> 2x LDG.64
            const float2* p = reinterpret_cast<const float2*>(rowp + j0);
            float2 a = __ldg(p);
            float2 b = __ldg(p + 1);
            v = make_float4(a.x, a.y, b.x, b.y);
        } else if (j0 >= start) {
            // Fully post-crop: contiguous shifted, j0+CROP even -> 2x LDG.64
            const float2* p = reinterpret_cast<const float2*>(rowp + j0 + CROP_NUM);
            float2 a = __ldg(p);
            float2 b = __ldg(p + 1);
            v = make_float4(a.x, a.y, b.x, b.y);
        } else {
            // Straddles the crop boundary (once per row): scalar selects
            unsigned int j;
            j = j0;      v.x = __ldg(&rowp[j + (j >= start ? CROP_NUM : 0u)]);
            j = j0 + 1u; v.y = __ldg(&rowp[j + (j >= start ? CROP_NUM : 0u)]);
            j = j0 + 2u; v.z = __ldg(&rowp[j + (j >= start ? CROP_NUM : 0u)]);
            j = j0 + 3u; v.w = __ldg(&rowp[j + (j >= start ? CROP_NUM : 0u)]);
        }
        reinterpret_cast<float4*>(out)[t] = v;
    } else {
        // Vector straddles a row boundary (<=127 total): fully scalar
        #pragma unroll
        for (int k = 0; k < 4; ++k) {
            unsigned int f  = f0 + (unsigned int)k;
            unsigned int ii = f / OUT_LEN;
            unsigned int jj = f - ii * OUT_LEN;
            unsigned int st = (unsigned int)__ldg(&starts[ii]);
            out[f] = __ldg(&audio[(size_t)ii * L_IN + jj + (jj >= st ? CROP_NUM : 0u)]);
        }
    }
}

__global__ __launch_bounds__(256)
void Crop_21345987461560_kernel(const float* __restrict__ audio,
                                const int*   __restrict__ starts,
                                float*       __restrict__ out)
{
    unsigned int t = blockIdx.x * blockDim.x + threadIdx.x;
    if (t < HALFVEC) {
        process_vec(t,           audio, starts, out);
        process_vec(t + HALFVEC, audio, starts, out);
    }
}

extern "C" void kernel_launch(void* const* d_in, const int* in_sizes, int n_in,
                              void* d_out, int out_size)
{
    const float* audio  = (const float*)d_in[0];   // [128, 262144] float32
    const int*   starts = (const int*)d_in[1];     // [128] int32
    float*       out    = (float*)d_out;           // [128, 235930] float32

    const unsigned int threads = 256;
    const unsigned int blocks  = (HALFVEC + threads - 1) / threads;  // 14746
    Crop_21345987461560_kernel<<<blocks, threads>>>(audio, starts, out);
}